// round 1
// baseline (speedup 1.0000x reference)
#include <cuda_runtime.h>
#include <cuda_bf16.h>
#include <cstdint>

// ---------------------------------------------------------------------------
// TwinningEdgeAttention:
//   subj = segment_mean(edge_features, src, N)   [N,128]
//   obj  = segment_mean(edge_features, dst, N)   [N,128]
//   h    = relu([subj,obj] @ W1 + b1)            [N,128]
//   out  = sigmoid(h @ W2 + b2)                  [N,128]
// ---------------------------------------------------------------------------

#define MAXN 65536
#define DE   128

// Scratch (static device globals: no allocation allowed in kernel_launch)
__device__ float g_subj[MAXN * DE];
__device__ float g_obj [MAXN * DE];
__device__ float g_cnt_src[MAXN];
__device__ float g_cnt_dst[MAXN];
__device__ float g_combined[MAXN * 2 * DE];  // [N, 256]
__device__ float g_h[MAXN * DE];             // [N, 128]
__device__ int   g_idx_is64;

// --- dtype sniffer: edge_index declared int64 in the reference, but JAX
// without x64 silently emits int32. Indices are < 2^31, so if the data is
// int64 every odd 32-bit word is exactly 0. P(false positive for int32
// random indices) = (2e-5)^256 ~ 0.
__global__ void detect_kernel(const int* __restrict__ ei_words) {
    if (threadIdx.x == 0 && blockIdx.x == 0) {
        int is64 = 1;
        for (int i = 0; i < 256; i++) {
            if (ei_words[2 * i + 1] != 0) { is64 = 0; break; }
        }
        g_idx_is64 = is64;
    }
}

__global__ void zero_kernel(int n) {
    const float4 z = make_float4(0.f, 0.f, 0.f, 0.f);
    int total4 = n * (DE / 4);
    int stride = gridDim.x * blockDim.x;
    for (int i = blockIdx.x * blockDim.x + threadIdx.x; i < total4; i += stride) {
        reinterpret_cast<float4*>(g_subj)[i] = z;
        reinterpret_cast<float4*>(g_obj)[i]  = z;
    }
    for (int i = blockIdx.x * blockDim.x + threadIdx.x; i < n; i += stride) {
        g_cnt_src[i] = 0.f;
        g_cnt_dst[i] = 0.f;
    }
}

// One warp per edge. Each lane owns 4 consecutive floats (float4),
// reduced into the node tables with red.global.add.v4.f32 (no return trip).
__global__ void scatter_kernel(const float* __restrict__ ef,
                               const void* __restrict__ ei_raw, int E) {
    int warp = (blockIdx.x * blockDim.x + threadIdx.x) >> 5;
    int lane = threadIdx.x & 31;
    if (warp >= E) return;

    long long s, d;
    if (g_idx_is64) {
        const long long* ei = (const long long*)ei_raw;
        s = ei[warp];
        d = ei[E + warp];
    } else {
        const int* ei = (const int*)ei_raw;
        s = ei[warp];
        d = ei[E + warp];
    }

    float4 v = reinterpret_cast<const float4*>(ef + (size_t)warp * DE)[lane];

    float* ps = g_subj + (size_t)s * DE + lane * 4;
    float* po = g_obj  + (size_t)d * DE + lane * 4;
    asm volatile("red.global.add.v4.f32 [%0], {%1,%2,%3,%4};"
                 :: "l"(ps), "f"(v.x), "f"(v.y), "f"(v.z), "f"(v.w) : "memory");
    asm volatile("red.global.add.v4.f32 [%0], {%1,%2,%3,%4};"
                 :: "l"(po), "f"(v.x), "f"(v.y), "f"(v.z), "f"(v.w) : "memory");

    if (lane == 0) {
        atomicAdd(&g_cnt_src[s], 1.0f);
        atomicAdd(&g_cnt_dst[d], 1.0f);
    }
}

// Turn sums into means and build combined = [subj_mean, obj_mean]  [N,256]
__global__ void finalize_kernel(int n) {
    int idx = blockIdx.x * blockDim.x + threadIdx.x;  // over n*32 float4 chunks
    if (idx >= n * (DE / 4)) return;
    int node = idx >> 5;
    int c4   = idx & 31;

    float is = 1.f / fmaxf(g_cnt_src[node], 1.f);
    float io = 1.f / fmaxf(g_cnt_dst[node], 1.f);

    float4 s = reinterpret_cast<const float4*>(g_subj)[idx];
    float4 o = reinterpret_cast<const float4*>(g_obj)[idx];
    s.x *= is; s.y *= is; s.z *= is; s.w *= is;
    o.x *= io; o.y *= io; o.z *= io; o.w *= io;

    float4* cmb = reinterpret_cast<float4*>(g_combined);
    cmb[(size_t)node * 64 + c4]      = s;  // cols [0,128)
    cmb[(size_t)node * 64 + 32 + c4] = o;  // cols [128,256)
}

// Register-tiled fp32 GEMM: C[n,128] = epi(A[n,K] @ B[K,128] + bias)
// PHASE 1: A = g_combined (K=256), epi = relu,    C = g_h
// PHASE 2: A = g_h        (K=128), epi = sigmoid, C = d_out
// Block: 256 threads, tile BM=64 x BN=128, thread tile 4x8.
template <int PHASE>
__global__ void __launch_bounds__(256)
gemm_kernel(const float* __restrict__ B, const float* __restrict__ bias,
            float* __restrict__ Cout, int n) {
    constexpr int K = (PHASE == 1) ? 256 : 128;
    const float* A = (PHASE == 1) ? g_combined : g_h;
    float* C = (PHASE == 1) ? g_h : Cout;

    __shared__ float As[32][64];    // [k][m]  (A stored transposed)
    __shared__ float Bs[32][128];   // [k][n]

    int tid = threadIdx.x;
    int tx = tid & 15;    // col group: cols tx*8 .. tx*8+7
    int ty = tid >> 4;    // row group: rows ty*4 .. ty*4+3
    int rowBase = blockIdx.x * 64;

    float acc[4][8];
#pragma unroll
    for (int i = 0; i < 4; i++)
#pragma unroll
        for (int j = 0; j < 8; j++) acc[i][j] = 0.f;

    for (int k0 = 0; k0 < K; k0 += 32) {
        // Load A tile 64x32 (512 float4), store transposed into As[k][m].
#pragma unroll
        for (int i = 0; i < 2; i++) {
            int idx = tid + 256 * i;      // 0..511
            int r   = idx >> 3;           // 0..63
            int c4  = idx & 7;            // 0..7
            float4 v = *reinterpret_cast<const float4*>(
                A + (size_t)(rowBase + r) * K + k0 + c4 * 4);
            As[c4 * 4 + 0][r] = v.x;
            As[c4 * 4 + 1][r] = v.y;
            As[c4 * 4 + 2][r] = v.z;
            As[c4 * 4 + 3][r] = v.w;
        }
        // Load B tile 32x128 (1024 float4), direct copy.
#pragma unroll
        for (int i = 0; i < 4; i++) {
            int idx = tid + 256 * i;      // 0..1023
            int r   = idx >> 5;           // 0..31
            int c4  = idx & 31;           // 0..31
            *reinterpret_cast<float4*>(&Bs[r][c4 * 4]) =
                *reinterpret_cast<const float4*>(B + (size_t)(k0 + r) * 128 + c4 * 4);
        }
        __syncthreads();

#pragma unroll
        for (int k = 0; k < 32; k++) {
            float4 a  = *reinterpret_cast<float4*>(&As[k][ty * 4]);
            float4 b0 = *reinterpret_cast<float4*>(&Bs[k][tx * 8]);
            float4 b1 = *reinterpret_cast<float4*>(&Bs[k][tx * 8 + 4]);
            float av[4] = {a.x, a.y, a.z, a.w};
            float bv[8] = {b0.x, b0.y, b0.z, b0.w, b1.x, b1.y, b1.z, b1.w};
#pragma unroll
            for (int i = 0; i < 4; i++)
#pragma unroll
                for (int j = 0; j < 8; j++)
                    acc[i][j] = fmaf(av[i], bv[j], acc[i][j]);
        }
        __syncthreads();
    }

    // Epilogue: bias + relu/sigmoid, vectorized float4 stores.
    float bb[8];
#pragma unroll
    for (int j = 0; j < 8; j++) bb[j] = bias[tx * 8 + j];

#pragma unroll
    for (int i = 0; i < 4; i++) {
        int r = rowBase + ty * 4 + i;
        if (r < n) {
            float o[8];
#pragma unroll
            for (int j = 0; j < 8; j++) {
                float x = acc[i][j] + bb[j];
                if (PHASE == 1) {
                    o[j] = fmaxf(x, 0.f);
                } else {
                    o[j] = 1.f / (1.f + expf(-x));
                }
            }
            float4* dst = reinterpret_cast<float4*>(C + (size_t)r * 128 + tx * 8);
            dst[0] = make_float4(o[0], o[1], o[2], o[3]);
            dst[1] = make_float4(o[4], o[5], o[6], o[7]);
        }
    }
}

extern "C" void kernel_launch(void* const* d_in, const int* in_sizes, int n_in,
                              void* d_out, int out_size) {
    // metadata order: edge_features, W1, b1, W2, b2, edge_index, num_nodes
    const float* ef = (const float*)d_in[0];
    const float* W1 = (const float*)d_in[1];
    const float* b1 = (const float*)d_in[2];
    const float* W2 = (const float*)d_in[3];
    const float* b2 = (const float*)d_in[4];
    const void*  ei = d_in[5];

    int E = in_sizes[5] / 2;     // edge_index is (2, E)
    int n = out_size / 128;      // output is [N, 128]

    detect_kernel<<<1, 32>>>((const int*)ei);
    zero_kernel<<<1024, 256>>>(n);
    scatter_kernel<<<(E + 7) / 8, 256>>>(ef, ei, E);

    int fin_threads = n * (DE / 4);
    finalize_kernel<<<(fin_threads + 255) / 256, 256>>>(n);

    int gblocks = (n + 63) / 64;
    gemm_kernel<1><<<gblocks, 256>>>(W1, b1, nullptr, n);
    gemm_kernel<2><<<gblocks, 256>>>(W2, b2, (float*)d_out, n);
}

// round 3
// speedup vs baseline: 1.9808x; 1.9808x over previous
#include <cuda_runtime.h>
#include <cuda_bf16.h>
#include <cstdint>

// ---------------------------------------------------------------------------
// TwinningEdgeAttention on GB300 (family-portable ISA only — no tcgen05):
//   scatter-mean (REDG.v4) -> fused HMMA bf16 GEMM chain (mma.sync m16n8k16):
//   h = relu([subj_mean,obj_mean] @ W1 + b1);  out = sigmoid(h @ W2 + b2)
// ---------------------------------------------------------------------------

#define MAXN 65536
#define DE   128

__device__ float g_subj[MAXN * DE];
__device__ float g_obj [MAXN * DE];
__device__ float g_cnt_src[MAXN];
__device__ float g_cnt_dst[MAXN];
__device__ int   g_idx_is64;

// ========================= helpers =========================================

__device__ __forceinline__ uint32_t smem_u32(const void* p) {
    uint32_t a;
    asm("{ .reg .u64 t; cvta.to.shared.u64 t, %1; cvt.u32.u64 %0, t; }"
        : "=r"(a) : "l"(p));
    return a;
}

// pack two fp32 -> bf16x2 (lo, hi)
__device__ __forceinline__ uint32_t pack_bf16(float lo, float hi) {
    uint32_t r;
    asm("cvt.rn.bf16x2.f32 %0, %1, %2;" : "=r"(r) : "f"(hi), "f"(lo));
    return r;
}

__device__ __forceinline__ void sts64(uint32_t addr, uint32_t a, uint32_t b) {
    asm volatile("st.shared.v2.b32 [%0], {%1,%2};" :: "r"(addr), "r"(a), "r"(b) : "memory");
}

__device__ __forceinline__ void ldm_x4(uint32_t addr, uint32_t* r) {
    asm volatile("ldmatrix.sync.aligned.m8n8.x4.shared.b16 {%0,%1,%2,%3}, [%4];"
                 : "=r"(r[0]), "=r"(r[1]), "=r"(r[2]), "=r"(r[3]) : "r"(addr));
}

__device__ __forceinline__ void ldm_x4_t(uint32_t addr, uint32_t* r) {
    asm volatile("ldmatrix.sync.aligned.m8n8.x4.trans.shared.b16 {%0,%1,%2,%3}, [%4];"
                 : "=r"(r[0]), "=r"(r[1]), "=r"(r[2]), "=r"(r[3]) : "r"(addr));
}

__device__ __forceinline__ void mma_bf16(float* d, const uint32_t* a, const uint32_t* b) {
    asm volatile("mma.sync.aligned.m16n8k16.row.col.f32.bf16.bf16.f32 "
                 "{%0,%1,%2,%3}, {%4,%5,%6,%7}, {%8,%9}, {%0,%1,%2,%3};"
                 : "+f"(d[0]), "+f"(d[1]), "+f"(d[2]), "+f"(d[3])
                 : "r"(a[0]), "r"(a[1]), "r"(a[2]), "r"(a[3]), "r"(b[0]), "r"(b[1]));
}

// ========================= pre-GEMM kernels ================================

__global__ void detect_kernel(const int* __restrict__ ei_words) {
    if (threadIdx.x == 0 && blockIdx.x == 0) {
        int is64 = 1;
        for (int i = 0; i < 256; i++) {
            if (ei_words[2 * i + 1] != 0) { is64 = 0; break; }
        }
        g_idx_is64 = is64;
    }
}

__global__ void zero_kernel(int n) {
    const float4 z = make_float4(0.f, 0.f, 0.f, 0.f);
    int total4 = n * (DE / 4);
    int stride = gridDim.x * blockDim.x;
    for (int i = blockIdx.x * blockDim.x + threadIdx.x; i < total4; i += stride) {
        reinterpret_cast<float4*>(g_subj)[i] = z;
        reinterpret_cast<float4*>(g_obj)[i]  = z;
    }
    for (int i = blockIdx.x * blockDim.x + threadIdx.x; i < n; i += stride) {
        g_cnt_src[i] = 0.f;
        g_cnt_dst[i] = 0.f;
    }
}

__global__ void scatter_kernel(const float* __restrict__ ef,
                               const void* __restrict__ ei_raw, int E) {
    int warp = (blockIdx.x * blockDim.x + threadIdx.x) >> 5;
    int lane = threadIdx.x & 31;
    if (warp >= E) return;

    long long s, d;
    if (g_idx_is64) {
        const long long* ei = (const long long*)ei_raw;
        s = ei[warp];
        d = ei[E + warp];
    } else {
        const int* ei = (const int*)ei_raw;
        s = ei[warp];
        d = ei[E + warp];
    }

    float4 v = reinterpret_cast<const float4*>(ef + (size_t)warp * DE)[lane];

    float* ps = g_subj + (size_t)s * DE + lane * 4;
    float* po = g_obj  + (size_t)d * DE + lane * 4;
    asm volatile("red.global.add.v4.f32 [%0], {%1,%2,%3,%4};"
                 :: "l"(ps), "f"(v.x), "f"(v.y), "f"(v.z), "f"(v.w) : "memory");
    asm volatile("red.global.add.v4.f32 [%0], {%1,%2,%3,%4};"
                 :: "l"(po), "f"(v.x), "f"(v.y), "f"(v.z), "f"(v.w) : "memory");

    if (lane == 0) {
        atomicAdd(&g_cnt_src[s], 1.0f);
        atomicAdd(&g_cnt_dst[d], 1.0f);
    }
}

// ========================= fused HMMA MLP ==================================
// Persistent over 128-row tiles. 256 threads = 8 warps (4 m-warps x 2 n-warps),
// each warp owns a 32x64 output block (2 m16-tiles x 8 n8-tiles).
// smem layout (bytes):
//   b1s[128]f32 @0, b2s[128]f32 @512, invs[128] @1024, invo[128] @1536,
//   As bf16 [128][72]  @2048   (18432 B)
//   Bs bf16 [64][136]  @20480  (17408 B)
//   Hs bf16 [128][136] @37888  (34816 B)
static constexpr int OFF_B1 = 0, OFF_B2 = 512, OFF_IS = 1024, OFF_IO = 1536;
static constexpr int OFF_AS = 2048, OFF_BS = 20480, OFF_HS = 37888;
static constexpr int LDA = 72, LDB = 136, LDH = 136;
static constexpr int SMEM_BYTES = 37888 + 34816;

__global__ void __launch_bounds__(256, 2)
fused_mlp(const float* __restrict__ W1, const float* __restrict__ b1,
          const float* __restrict__ W2, const float* __restrict__ b2,
          float* __restrict__ out, int n)
{
    extern __shared__ char smem[];
    const uint32_t sb = smem_u32(smem);
    const int tid = threadIdx.x, wid = tid >> 5, lane = tid & 31;

    float* b1s  = (float*)(smem + OFF_B1);
    float* b2s  = (float*)(smem + OFF_B2);
    float* invs = (float*)(smem + OFF_IS);
    float* invo = (float*)(smem + OFF_IO);

    const int warp_m = (wid & 3) * 32;
    const int warp_n = (wid >> 2) * 64;

    // ldmatrix lane addressing pieces
    const int lm_row = lane & 15;           // row within 16
    const int lm_col = (lane >> 4) * 8;     // 0 or 8

    if (tid < 128) { b1s[tid] = b1[tid]; b2s[tid] = b2[tid]; }

    const int TILES = (n + 127) >> 7;
    for (int tile = blockIdx.x; tile < TILES; tile += gridDim.x) {
        const int row0 = tile << 7;

        if (tid < 128) {
            int r = row0 + tid;
            invs[tid] = (r < n) ? 1.f / fmaxf(g_cnt_src[r], 1.f) : 0.f;
            invo[tid] = (r < n) ? 1.f / fmaxf(g_cnt_dst[r], 1.f) : 0.f;
        }

        float d[2][8][4];
#pragma unroll
        for (int i = 0; i < 2; i++)
#pragma unroll
            for (int j = 0; j < 8; j++)
#pragma unroll
                for (int k = 0; k < 4; k++) d[i][j][k] = 0.f;

        // ================= phase 1: [128x256] @ W1 -> D =================
        for (int kc = 0; kc < 4; kc++) {
            __syncthreads();
            const float* src  = (kc < 2) ? g_subj : g_obj;
            const float* invp = (kc < 2) ? invs : invo;
            const int cb = (kc & 1) * 64;
            // fill As: 128 x 64 bf16 (scaled means)
#pragma unroll
            for (int i = 0; i < 8; i++) {
                int idx = tid + 256 * i;          // 0..2047
                int r = idx >> 4, c4 = idx & 15;  // r:0..127, c4:0..15
                int gr = row0 + r;
                float4 v = make_float4(0.f, 0.f, 0.f, 0.f);
                if (gr < n) {
                    v = *(const float4*)(src + (size_t)gr * 128 + cb + c4 * 4);
                    float s = invp[r];
                    v.x *= s; v.y *= s; v.z *= s; v.w *= s;
                }
                sts64(sb + OFF_AS + (r * LDA + c4 * 4) * 2,
                      pack_bf16(v.x, v.y), pack_bf16(v.z, v.w));
            }
            // fill Bs: W1 rows [kc*64, kc*64+64) x 128 cols
#pragma unroll
            for (int i = 0; i < 8; i++) {
                int idx = tid + 256 * i;
                int r = idx >> 5, c4 = idx & 31;  // r:0..63, c4:0..31
                float4 w = *(const float4*)(W1 + (size_t)(kc * 64 + r) * 128 + c4 * 4);
                sts64(sb + OFF_BS + (r * LDB + c4 * 4) * 2,
                      pack_bf16(w.x, w.y), pack_bf16(w.z, w.w));
            }
            __syncthreads();

#pragma unroll
            for (int ks = 0; ks < 4; ks++) {
                uint32_t a[2][4], bq[4][4];
#pragma unroll
                for (int tm = 0; tm < 2; tm++)
                    ldm_x4(sb + OFF_AS + ((warp_m + tm * 16 + lm_row) * LDA
                                          + ks * 16 + lm_col) * 2, a[tm]);
#pragma unroll
                for (int tb = 0; tb < 4; tb++)
                    ldm_x4_t(sb + OFF_BS + ((ks * 16 + lm_row) * LDB
                                            + warp_n + tb * 16 + lm_col) * 2, bq[tb]);
#pragma unroll
                for (int tm = 0; tm < 2; tm++)
#pragma unroll
                    for (int tn = 0; tn < 8; tn++)
                        mma_bf16(d[tm][tn], a[tm], &bq[tn >> 1][(tn & 1) * 2]);
            }
        }

        // ---- epilogue 1: relu(D + b1) -> Hs (bf16) ----
        {
            int rb = warp_m + (lane >> 2);
            int cb = warp_n + (lane & 3) * 2;
#pragma unroll
            for (int tm = 0; tm < 2; tm++)
#pragma unroll
                for (int tn = 0; tn < 8; tn++) {
                    int row = rb + tm * 16, col = cb + tn * 8;
                    float x0 = fmaxf(d[tm][tn][0] + b1s[col],     0.f);
                    float x1 = fmaxf(d[tm][tn][1] + b1s[col + 1], 0.f);
                    float x2 = fmaxf(d[tm][tn][2] + b1s[col],     0.f);
                    float x3 = fmaxf(d[tm][tn][3] + b1s[col + 1], 0.f);
                    *(uint32_t*)(smem + OFF_HS + (row * LDH + col) * 2)       = pack_bf16(x0, x1);
                    *(uint32_t*)(smem + OFF_HS + ((row + 8) * LDH + col) * 2) = pack_bf16(x2, x3);
                }
        }

        // reset accumulators for phase 2
#pragma unroll
        for (int i = 0; i < 2; i++)
#pragma unroll
            for (int j = 0; j < 8; j++)
#pragma unroll
                for (int k = 0; k < 4; k++) d[i][j][k] = 0.f;

        // ================= phase 2: Hs[128x128] @ W2 -> D ================
        for (int kc = 0; kc < 2; kc++) {
            __syncthreads();
#pragma unroll
            for (int i = 0; i < 8; i++) {
                int idx = tid + 256 * i;
                int r = idx >> 5, c4 = idx & 31;
                float4 w = *(const float4*)(W2 + (size_t)(kc * 64 + r) * 128 + c4 * 4);
                sts64(sb + OFF_BS + (r * LDB + c4 * 4) * 2,
                      pack_bf16(w.x, w.y), pack_bf16(w.z, w.w));
            }
            __syncthreads();

#pragma unroll
            for (int ks = 0; ks < 4; ks++) {
                uint32_t a[2][4], bq[4][4];
#pragma unroll
                for (int tm = 0; tm < 2; tm++)
                    ldm_x4(sb + OFF_HS + ((warp_m + tm * 16 + lm_row) * LDH
                                          + kc * 64 + ks * 16 + lm_col) * 2, a[tm]);
#pragma unroll
                for (int tb = 0; tb < 4; tb++)
                    ldm_x4_t(sb + OFF_BS + ((ks * 16 + lm_row) * LDB
                                            + warp_n + tb * 16 + lm_col) * 2, bq[tb]);
#pragma unroll
                for (int tm = 0; tm < 2; tm++)
#pragma unroll
                    for (int tn = 0; tn < 8; tn++)
                        mma_bf16(d[tm][tn], a[tm], &bq[tn >> 1][(tn & 1) * 2]);
            }
        }

        // ---- epilogue 2: sigmoid(D + b2) -> gmem ----
        {
            int rb = warp_m + (lane >> 2);
            int cb = warp_n + (lane & 3) * 2;
#pragma unroll
            for (int tm = 0; tm < 2; tm++)
#pragma unroll
                for (int tn = 0; tn < 8; tn++) {
                    int row = rb + tm * 16, col = cb + tn * 8;
                    int gr0 = row0 + row, gr1 = gr0 + 8;
                    if (gr0 < n) {
                        float2 o;
                        o.x = 1.f / (1.f + __expf(-(d[tm][tn][0] + b2s[col])));
                        o.y = 1.f / (1.f + __expf(-(d[tm][tn][1] + b2s[col + 1])));
                        *(float2*)(out + (size_t)gr0 * 128 + col) = o;
                    }
                    if (gr1 < n) {
                        float2 o;
                        o.x = 1.f / (1.f + __expf(-(d[tm][tn][2] + b2s[col])));
                        o.y = 1.f / (1.f + __expf(-(d[tm][tn][3] + b2s[col + 1])));
                        *(float2*)(out + (size_t)gr1 * 128 + col) = o;
                    }
                }
        }
        __syncthreads();  // protect invs/invo + smem reuse next tile
    }
}

// ========================= launch ==========================================

extern "C" void kernel_launch(void* const* d_in, const int* in_sizes, int n_in,
                              void* d_out, int out_size) {
    const float* ef = (const float*)d_in[0];
    const float* W1 = (const float*)d_in[1];
    const float* b1 = (const float*)d_in[2];
    const float* W2 = (const float*)d_in[3];
    const float* b2 = (const float*)d_in[4];
    const void*  ei = d_in[5];

    int E = in_sizes[5] / 2;
    int n = out_size / 128;

    detect_kernel<<<1, 32>>>((const int*)ei);
    zero_kernel<<<1024, 256>>>(n);
    scatter_kernel<<<(E + 7) / 8, 256>>>(ef, ei, E);

    cudaFuncSetAttribute(fused_mlp, cudaFuncAttributeMaxDynamicSharedMemorySize, SMEM_BYTES);
    int TILES = (n + 127) / 128;
    int grid = TILES < 296 ? TILES : 296;
    fused_mlp<<<grid, 256, SMEM_BYTES>>>(W1, b1, W2, b2, (float*)d_out, n);
}

// round 5
// speedup vs baseline: 2.8889x; 1.4585x over previous
#include <cuda_runtime.h>
#include <cuda_fp16.h>
#include <cuda_bf16.h>
#include <cstdint>

// ---------------------------------------------------------------------------
// TwinningEdgeAttention on GB300:
//   scatter-mean: fp16 accumulation tables via red.global.add.noftz.v4.f16x2
//                 (8 values / 128-bit REDG, one warp per 2 edges)
//   fused HMMA bf16 MLP: weights resident in smem, 4 syncs/tile, 512 thr/CTA
// ---------------------------------------------------------------------------

#define MAXN 65536
#define DE   128

__device__ __align__(256) __half g_subj16[MAXN * DE];
__device__ __align__(256) __half g_obj16 [MAXN * DE];
__device__ float g_cnt_src[MAXN];
__device__ float g_cnt_dst[MAXN];
__device__ int   g_idx_is64;

// ========================= helpers =========================================

__device__ __forceinline__ uint32_t smem_u32(const void* p) {
    uint32_t a;
    asm("{ .reg .u64 t; cvta.to.shared.u64 t, %1; cvt.u32.u64 %0, t; }"
        : "=r"(a) : "l"(p));
    return a;
}

__device__ __forceinline__ uint32_t pack_bf16(float lo, float hi) {
    uint32_t r;
    asm("cvt.rn.bf16x2.f32 %0, %1, %2;" : "=r"(r) : "f"(hi), "f"(lo));
    return r;
}

__device__ __forceinline__ uint32_t pack_f16(float lo, float hi) {
    uint32_t r;
    asm("cvt.rn.f16x2.f32 %0, %1, %2;" : "=r"(r) : "f"(hi), "f"(lo));
    return r;
}

__device__ __forceinline__ void sts64(uint32_t addr, uint32_t a, uint32_t b) {
    asm volatile("st.shared.v2.b32 [%0], {%1,%2};" :: "r"(addr), "r"(a), "r"(b) : "memory");
}

__device__ __forceinline__ void sts128(uint32_t addr, uint32_t a, uint32_t b,
                                       uint32_t c, uint32_t d) {
    asm volatile("st.shared.v4.b32 [%0], {%1,%2,%3,%4};"
                 :: "r"(addr), "r"(a), "r"(b), "r"(c), "r"(d) : "memory");
}

__device__ __forceinline__ void ldm_x4(uint32_t addr, uint32_t* r) {
    asm volatile("ldmatrix.sync.aligned.m8n8.x4.shared.b16 {%0,%1,%2,%3}, [%4];"
                 : "=r"(r[0]), "=r"(r[1]), "=r"(r[2]), "=r"(r[3]) : "r"(addr));
}

__device__ __forceinline__ void ldm_x4_t(uint32_t addr, uint32_t* r) {
    asm volatile("ldmatrix.sync.aligned.m8n8.x4.trans.shared.b16 {%0,%1,%2,%3}, [%4];"
                 : "=r"(r[0]), "=r"(r[1]), "=r"(r[2]), "=r"(r[3]) : "r"(addr));
}

__device__ __forceinline__ void mma_bf16(float* d, const uint32_t* a, const uint32_t* b) {
    asm volatile("mma.sync.aligned.m16n8k16.row.col.f32.bf16.bf16.f32 "
                 "{%0,%1,%2,%3}, {%4,%5,%6,%7}, {%8,%9}, {%0,%1,%2,%3};"
                 : "+f"(d[0]), "+f"(d[1]), "+f"(d[2]), "+f"(d[3])
                 : "r"(a[0]), "r"(a[1]), "r"(a[2]), "r"(a[3]), "r"(b[0]), "r"(b[1]));
}

// 128-bit fp16 reduction: adds 8 halves in one REDG
__device__ __forceinline__ void red_v4h2(__half* p, uint32_t a, uint32_t b,
                                         uint32_t c, uint32_t d) {
    asm volatile("red.global.add.noftz.v4.f16x2 [%0], {%1,%2,%3,%4};"
                 :: "l"(p), "r"(a), "r"(b), "r"(c), "r"(d) : "memory");
}

// ========================= pre-GEMM kernels ================================

__global__ void detect_kernel(const int* __restrict__ ei_words) {
    if (threadIdx.x == 0 && blockIdx.x == 0) {
        int is64 = 1;
        for (int i = 0; i < 256; i++) {
            if (ei_words[2 * i + 1] != 0) { is64 = 0; break; }
        }
        g_idx_is64 = is64;
    }
}

__global__ void zero_kernel(int n) {
    const uint4 z = make_uint4(0, 0, 0, 0);
    int total16 = n * (DE / 8);   // 16B chunks per table
    int stride = gridDim.x * blockDim.x;
    for (int i = blockIdx.x * blockDim.x + threadIdx.x; i < total16; i += stride) {
        reinterpret_cast<uint4*>(g_subj16)[i] = z;
        reinterpret_cast<uint4*>(g_obj16)[i]  = z;
    }
    for (int i = blockIdx.x * blockDim.x + threadIdx.x; i < n; i += stride) {
        g_cnt_src[i] = 0.f;
        g_cnt_dst[i] = 0.f;
    }
}

// One warp per TWO edges: lanes 0-15 own edge0, lanes 16-31 own edge1.
// Each lane owns 8 consecutive features -> one v4.f16x2 REDG per table.
__global__ void scatter_kernel(const float* __restrict__ ef,
                               const void* __restrict__ ei_raw, long long E) {
    long long gw = (long long)(blockIdx.x * blockDim.x + threadIdx.x) >> 5;
    int lane = threadIdx.x & 31;
    int half = lane >> 4;
    int grp  = lane & 15;
    long long edge = 2 * gw + half;
    if (edge >= E) return;

    long long s, d;
    if (g_idx_is64) {
        const long long* ei = (const long long*)ei_raw;
        s = ei[edge];
        d = ei[E + edge];
    } else {
        const int* ei = (const int*)ei_raw;
        s = ei[edge];
        d = ei[E + edge];
    }

    const float4* row = (const float4*)(ef + (size_t)edge * DE + grp * 8);
    float4 v0 = row[0];
    float4 v1 = row[1];
    uint32_t h0 = pack_f16(v0.x, v0.y);
    uint32_t h1 = pack_f16(v0.z, v0.w);
    uint32_t h2 = pack_f16(v1.x, v1.y);
    uint32_t h3 = pack_f16(v1.z, v1.w);

    red_v4h2(g_subj16 + (size_t)s * DE + grp * 8, h0, h1, h2, h3);
    red_v4h2(g_obj16  + (size_t)d * DE + grp * 8, h0, h1, h2, h3);

    if (grp == 0) {
        atomicAdd(&g_cnt_src[s], 1.0f);
        atomicAdd(&g_cnt_dst[d], 1.0f);
    }
}

// ========================= fused HMMA MLP ==================================
// 512 threads = 16 warps (4 m-warps x 4 n-warps), warp tile 32x32.
// Weights resident in smem across all tiles (loaded once per CTA).
// smem layout (bytes):
//   b1s[128] @0, b2s[128] @512, invs[128] @1024, invo[128] @1536
//   W1s bf16 [256][136] @2048    (69632)
//   W2s bf16 [128][136] @71680   (34816)
//   Hs  bf16 [128][136] @106496  (34816)
//   As  bf16 [128][264] @141312  (67584)  -> total 208896
static constexpr int OFF_B1 = 0, OFF_B2 = 512, OFF_IS = 1024, OFF_IO = 1536;
static constexpr int OFF_W1 = 2048, OFF_W2 = 71680, OFF_HS = 106496, OFF_AS = 141312;
static constexpr int LDW = 136, LDH = 136, LDA = 264;
static constexpr int SMEM_BYTES = 208896;

__global__ void __launch_bounds__(512, 1)
fused_mlp(const float* __restrict__ W1, const float* __restrict__ b1,
          const float* __restrict__ W2, const float* __restrict__ b2,
          float* __restrict__ out, int n)
{
    extern __shared__ char smem[];
    const uint32_t sb = smem_u32(smem);
    const int tid = threadIdx.x, wid = tid >> 5, lane = tid & 31;

    float* b1s  = (float*)(smem + OFF_B1);
    float* b2s  = (float*)(smem + OFF_B2);
    float* invs = (float*)(smem + OFF_IS);
    float* invo = (float*)(smem + OFF_IO);

    const int warp_m = (wid & 3) * 32;
    const int warp_n = (wid >> 2) * 32;
    const int lm_row = lane & 15;
    const int lm_col = (lane >> 4) * 8;

    // ---- one-time: weights + biases -> smem (bf16) ----
    if (tid < 128) { b1s[tid] = b1[tid]; b2s[tid] = b2[tid]; }
#pragma unroll
    for (int i = 0; i < 16; i++) {                 // W1: 256x128 fp32
        int idx = tid + 512 * i;
        int r = idx >> 5, c4 = idx & 31;
        float4 w = *(const float4*)(W1 + (size_t)r * 128 + c4 * 4);
        sts64(sb + OFF_W1 + (r * LDW + c4 * 4) * 2, pack_bf16(w.x, w.y), pack_bf16(w.z, w.w));
    }
#pragma unroll
    for (int i = 0; i < 8; i++) {                  // W2: 128x128 fp32
        int idx = tid + 512 * i;
        int r = idx >> 5, c4 = idx & 31;
        float4 w = *(const float4*)(W2 + (size_t)r * 128 + c4 * 4);
        sts64(sb + OFF_W2 + (r * LDW + c4 * 4) * 2, pack_bf16(w.x, w.y), pack_bf16(w.z, w.w));
    }
    __syncthreads();

    const int TILES = (n + 127) >> 7;
    for (int tile = blockIdx.x; tile < TILES; tile += gridDim.x) {
        const int row0 = tile << 7;

        if (tid < 128) {
            int r = row0 + tid;
            invs[tid] = (r < n) ? 1.f / fmaxf(g_cnt_src[r], 1.f) : 0.f;
            invo[tid] = (r < n) ? 1.f / fmaxf(g_cnt_dst[r], 1.f) : 0.f;
        }
        __syncthreads();

        // ---- As fill: [128 rows][256 cols] = [subj_mean | obj_mean], bf16 ----
        // 128x256 elems in 16B (8-half) chunks: 4096 chunks / 512 thr = 8 iters
#pragma unroll
        for (int i = 0; i < 8; i++) {
            int idx = tid + 512 * i;              // 0..4095
            int r = idx >> 5, c8 = idx & 31;      // r:0..127, c8:0..31
            int gr = row0 + r;
            uint32_t o0 = 0, o1 = 0, o2 = 0, o3 = 0;
            if (gr < n) {
                const __half* src = (c8 < 16)
                    ? g_subj16 + (size_t)gr * DE + c8 * 8
                    : g_obj16  + (size_t)gr * DE + (c8 - 16) * 8;
                float s = (c8 < 16) ? invs[r] : invo[r];
                uint4 raw = *(const uint4*)src;
                const __half2* h2 = (const __half2*)&raw;
                float2 f0 = __half22float2(h2[0]);
                float2 f1 = __half22float2(h2[1]);
                float2 f2 = __half22float2(h2[2]);
                float2 f3 = __half22float2(h2[3]);
                o0 = pack_bf16(f0.x * s, f0.y * s);
                o1 = pack_bf16(f1.x * s, f1.y * s);
                o2 = pack_bf16(f2.x * s, f2.y * s);
                o3 = pack_bf16(f3.x * s, f3.y * s);
            }
            sts128(sb + OFF_AS + (r * LDA + c8 * 8) * 2, o0, o1, o2, o3);
        }
        __syncthreads();

        // ================= phase 1: As[128x256] @ W1s -> D ================
        float d[2][4][4];
#pragma unroll
        for (int i = 0; i < 2; i++)
#pragma unroll
            for (int j = 0; j < 4; j++)
#pragma unroll
                for (int k = 0; k < 4; k++) d[i][j][k] = 0.f;

#pragma unroll
        for (int ks = 0; ks < 16; ks++) {
            uint32_t a[2][4], bq[2][4];
#pragma unroll
            for (int tm = 0; tm < 2; tm++)
                ldm_x4(sb + OFF_AS + ((warp_m + tm * 16 + lm_row) * LDA + ks * 16 + lm_col) * 2, a[tm]);
#pragma unroll
            for (int tb = 0; tb < 2; tb++)
                ldm_x4_t(sb + OFF_W1 + ((ks * 16 + lm_row) * LDW + warp_n + tb * 16 + lm_col) * 2, bq[tb]);
#pragma unroll
            for (int tm = 0; tm < 2; tm++)
#pragma unroll
                for (int tn = 0; tn < 4; tn++)
                    mma_bf16(d[tm][tn], a[tm], &bq[tn >> 1][(tn & 1) * 2]);
        }

        // ---- epilogue 1: relu(D + b1) -> Hs (bf16) ----
        {
            int rb = warp_m + (lane >> 2);
            int cb = warp_n + (lane & 3) * 2;
#pragma unroll
            for (int tm = 0; tm < 2; tm++)
#pragma unroll
                for (int tn = 0; tn < 4; tn++) {
                    int row = rb + tm * 16, col = cb + tn * 8;
                    float x0 = fmaxf(d[tm][tn][0] + b1s[col],     0.f);
                    float x1 = fmaxf(d[tm][tn][1] + b1s[col + 1], 0.f);
                    float x2 = fmaxf(d[tm][tn][2] + b1s[col],     0.f);
                    float x3 = fmaxf(d[tm][tn][3] + b1s[col + 1], 0.f);
                    *(uint32_t*)(smem + OFF_HS + (row * LDH + col) * 2)       = pack_bf16(x0, x1);
                    *(uint32_t*)(smem + OFF_HS + ((row + 8) * LDH + col) * 2) = pack_bf16(x2, x3);
                }
        }
        __syncthreads();

        // ================= phase 2: Hs[128x128] @ W2s -> D ================
#pragma unroll
        for (int i = 0; i < 2; i++)
#pragma unroll
            for (int j = 0; j < 4; j++)
#pragma unroll
                for (int k = 0; k < 4; k++) d[i][j][k] = 0.f;

#pragma unroll
        for (int ks = 0; ks < 8; ks++) {
            uint32_t a[2][4], bq[2][4];
#pragma unroll
            for (int tm = 0; tm < 2; tm++)
                ldm_x4(sb + OFF_HS + ((warp_m + tm * 16 + lm_row) * LDH + ks * 16 + lm_col) * 2, a[tm]);
#pragma unroll
            for (int tb = 0; tb < 2; tb++)
                ldm_x4_t(sb + OFF_W2 + ((ks * 16 + lm_row) * LDW + warp_n + tb * 16 + lm_col) * 2, bq[tb]);
#pragma unroll
            for (int tm = 0; tm < 2; tm++)
#pragma unroll
                for (int tn = 0; tn < 4; tn++)
                    mma_bf16(d[tm][tn], a[tm], &bq[tn >> 1][(tn & 1) * 2]);
        }

        // ---- epilogue 2: sigmoid(D + b2) -> gmem ----
        {
            int rb = warp_m + (lane >> 2);
            int cb = warp_n + (lane & 3) * 2;
#pragma unroll
            for (int tm = 0; tm < 2; tm++)
#pragma unroll
                for (int tn = 0; tn < 4; tn++) {
                    int row = rb + tm * 16, col = cb + tn * 8;
                    int gr0 = row0 + row, gr1 = gr0 + 8;
                    if (gr0 < n) {
                        float2 o;
                        o.x = 1.f / (1.f + __expf(-(d[tm][tn][0] + b2s[col])));
                        o.y = 1.f / (1.f + __expf(-(d[tm][tn][1] + b2s[col + 1])));
                        *(float2*)(out + (size_t)gr0 * 128 + col) = o;
                    }
                    if (gr1 < n) {
                        float2 o;
                        o.x = 1.f / (1.f + __expf(-(d[tm][tn][2] + b2s[col])));
                        o.y = 1.f / (1.f + __expf(-(d[tm][tn][3] + b2s[col + 1])));
                        *(float2*)(out + (size_t)gr1 * 128 + col) = o;
                    }
                }
        }
        __syncthreads();
    }
}

// ========================= launch ==========================================

extern "C" void kernel_launch(void* const* d_in, const int* in_sizes, int n_in,
                              void* d_out, int out_size) {
    const float* ef = (const float*)d_in[0];
    const float* W1 = (const float*)d_in[1];
    const float* b1 = (const float*)d_in[2];
    const float* W2 = (const float*)d_in[3];
    const float* b2 = (const float*)d_in[4];
    const void*  ei = d_in[5];

    long long E = in_sizes[5] / 2;
    int n = out_size / 128;

    detect_kernel<<<1, 32>>>((const int*)ei);
    zero_kernel<<<1024, 256>>>(n);

    long long warps = (E + 1) / 2;   // one warp per 2 edges
    int sblocks = (int)((warps * 32 + 255) / 256);
    scatter_kernel<<<sblocks, 256>>>(ef, ei, E);

    cudaFuncSetAttribute(fused_mlp, cudaFuncAttributeMaxDynamicSharedMemorySize, SMEM_BYTES);
    int TILES = (n + 127) / 128;
    int grid = TILES < 148 ? TILES : 148;
    fused_mlp<<<grid, 512, SMEM_BYTES>>>(W1, b1, W2, b2, (float*)d_out, n);
}

// round 6
// speedup vs baseline: 2.9944x; 1.0365x over previous
#include <cuda_runtime.h>
#include <cuda_fp16.h>
#include <cstdint>

// ---------------------------------------------------------------------------
// TwinningEdgeAttention on GB300:
//   scatter-mean: fp16 tables via red.global.add.noftz.v4.f16x2
//   MLP: fp16 HMMA, cp.async double-buffered 64-row tiles, weights in smem,
//        mean-scaling deferred to epilogue (raw sums feed the MMA directly)
// ---------------------------------------------------------------------------

#define MAXN 65536
#define DE   128

__device__ __align__(256) __half g_subj16[MAXN * DE];
__device__ __align__(256) __half g_obj16 [MAXN * DE];
__device__ float g_cnt_src[MAXN];
__device__ float g_cnt_dst[MAXN];
__device__ int   g_idx_is64;

// ========================= helpers =========================================

__device__ __forceinline__ uint32_t smem_u32(const void* p) {
    uint32_t a;
    asm("{ .reg .u64 t; cvta.to.shared.u64 t, %1; cvt.u32.u64 %0, t; }"
        : "=r"(a) : "l"(p));
    return a;
}

__device__ __forceinline__ uint32_t pack_f16(float lo, float hi) {
    uint32_t r;
    asm("cvt.rn.f16x2.f32 %0, %1, %2;" : "=r"(r) : "f"(hi), "f"(lo));
    return r;
}

__device__ __forceinline__ void sts64(uint32_t addr, uint32_t a, uint32_t b) {
    asm volatile("st.shared.v2.b32 [%0], {%1,%2};" :: "r"(addr), "r"(a), "r"(b) : "memory");
}

__device__ __forceinline__ void ldm_x4(uint32_t addr, uint32_t* r) {
    asm volatile("ldmatrix.sync.aligned.m8n8.x4.shared.b16 {%0,%1,%2,%3}, [%4];"
                 : "=r"(r[0]), "=r"(r[1]), "=r"(r[2]), "=r"(r[3]) : "r"(addr));
}

__device__ __forceinline__ void ldm_x4_t(uint32_t addr, uint32_t* r) {
    asm volatile("ldmatrix.sync.aligned.m8n8.x4.trans.shared.b16 {%0,%1,%2,%3}, [%4];"
                 : "=r"(r[0]), "=r"(r[1]), "=r"(r[2]), "=r"(r[3]) : "r"(addr));
}

__device__ __forceinline__ void mma_f16(float* d, const uint32_t* a, const uint32_t* b) {
    asm volatile("mma.sync.aligned.m16n8k16.row.col.f32.f16.f16.f32 "
                 "{%0,%1,%2,%3}, {%4,%5,%6,%7}, {%8,%9}, {%0,%1,%2,%3};"
                 : "+f"(d[0]), "+f"(d[1]), "+f"(d[2]), "+f"(d[3])
                 : "r"(a[0]), "r"(a[1]), "r"(a[2]), "r"(a[3]), "r"(b[0]), "r"(b[1]));
}

__device__ __forceinline__ void red_v4h2(__half* p, uint32_t a, uint32_t b,
                                         uint32_t c, uint32_t d) {
    asm volatile("red.global.add.noftz.v4.f16x2 [%0], {%1,%2,%3,%4};"
                 :: "l"(p), "r"(a), "r"(b), "r"(c), "r"(d) : "memory");
}

__device__ __forceinline__ void cp16(uint32_t dst, const void* src, int srcsize) {
    asm volatile("cp.async.cg.shared.global [%0], [%1], 16, %2;"
                 :: "r"(dst), "l"(src), "r"(srcsize) : "memory");
}
#define CP_COMMIT() asm volatile("cp.async.commit_group;" ::: "memory")
#define CP_WAIT1()  asm volatile("cp.async.wait_group 1;" ::: "memory")

// ========================= pre-GEMM kernels ================================

__global__ void detect_kernel(const int* __restrict__ ei_words) {
    if (threadIdx.x == 0 && blockIdx.x == 0) {
        int is64 = 1;
        for (int i = 0; i < 256; i++) {
            if (ei_words[2 * i + 1] != 0) { is64 = 0; break; }
        }
        g_idx_is64 = is64;
    }
}

__global__ void zero_kernel(int n) {
    const uint4 z = make_uint4(0, 0, 0, 0);
    int total16 = n * (DE / 8);
    int stride = gridDim.x * blockDim.x;
    for (int i = blockIdx.x * blockDim.x + threadIdx.x; i < total16; i += stride) {
        reinterpret_cast<uint4*>(g_subj16)[i] = z;
        reinterpret_cast<uint4*>(g_obj16)[i]  = z;
    }
    for (int i = blockIdx.x * blockDim.x + threadIdx.x; i < n; i += stride) {
        g_cnt_src[i] = 0.f;
        g_cnt_dst[i] = 0.f;
    }
}

// One warp per TWO edges: lanes 0-15 own edge0, lanes 16-31 own edge1.
__global__ void scatter_kernel(const float* __restrict__ ef,
                               const void* __restrict__ ei_raw, long long E) {
    long long gw = (long long)(blockIdx.x * blockDim.x + threadIdx.x) >> 5;
    int lane = threadIdx.x & 31;
    int half = lane >> 4;
    int grp  = lane & 15;
    long long edge = 2 * gw + half;
    if (edge >= E) return;

    long long s, d;
    if (g_idx_is64) {
        const long long* ei = (const long long*)ei_raw;
        s = ei[edge];
        d = ei[E + edge];
    } else {
        const int* ei = (const int*)ei_raw;
        s = ei[edge];
        d = ei[E + edge];
    }

    const float4* row = (const float4*)(ef + (size_t)edge * DE + grp * 8);
    float4 v0 = row[0];
    float4 v1 = row[1];
    uint32_t h0 = pack_f16(v0.x, v0.y);
    uint32_t h1 = pack_f16(v0.z, v0.w);
    uint32_t h2 = pack_f16(v1.x, v1.y);
    uint32_t h3 = pack_f16(v1.z, v1.w);

    red_v4h2(g_subj16 + (size_t)s * DE + grp * 8, h0, h1, h2, h3);
    red_v4h2(g_obj16  + (size_t)d * DE + grp * 8, h0, h1, h2, h3);

    if (grp == 0) {
        atomicAdd(&g_cnt_src[s], 1.0f);
        atomicAdd(&g_cnt_dst[d], 1.0f);
    }
}

// ========================= pipelined fp16 HMMA MLP =========================
// 512 threads = 16 warps (4 m x 4 n), warp tile 16x32, CTA tile 64x128.
// As fed by cp.async (raw fp16 sums), scaling deferred to epilogue.
// smem layout (bytes):
//   b1s[128]f32 @0, b2s[128]f32 @512, invs[64]f32 @1024, invo[64]f32 @1280
//   W1h fp16 [256][136] @1536    (69632)
//   W2h fp16 [128][136] @71168   (34816)
//   Hs  fp16 [64][136]  @105984  (17408)
//   As  fp16 [2][64][264] @123392 (2 x 33792)   -> total 190976
static constexpr int OFF_B1 = 0, OFF_B2 = 512, OFF_IS = 1024, OFF_IO = 1280;
static constexpr int OFF_W1 = 1536, OFF_W2 = 71168, OFF_HS = 105984, OFF_AS = 123392;
static constexpr int LDW = 136, LDH = 136, LDA = 264;
static constexpr int AS_BUF = 64 * LDA * 2;  // 33792
static constexpr int SMEM_BYTES = OFF_AS + 2 * AS_BUF;

__device__ __forceinline__ void prefetch_tile(uint32_t asbuf, int row0, int n, int tid) {
#pragma unroll
    for (int i = 0; i < 4; i++) {
        int idx = tid + 512 * i;              // 0..2047
        int r = idx >> 5, c8 = idx & 31;      // r:0..63, c8:0..31
        int gr = row0 + r;
        const __half* src = (c8 < 16)
            ? g_subj16 + (size_t)gr * DE + c8 * 8
            : g_obj16  + (size_t)gr * DE + (c8 - 16) * 8;
        int sz = (gr < n) ? 16 : 0;
        cp16(asbuf + (r * LDA + c8 * 8) * 2, src, sz);
    }
}

__global__ void __launch_bounds__(512, 1)
fused_mlp(const float* __restrict__ W1, const float* __restrict__ b1,
          const float* __restrict__ W2, const float* __restrict__ b2,
          float* __restrict__ out, int n)
{
    extern __shared__ char smem[];
    const uint32_t sb = smem_u32(smem);
    const int tid = threadIdx.x, wid = tid >> 5, lane = tid & 31;

    float* b1s  = (float*)(smem + OFF_B1);
    float* b2s  = (float*)(smem + OFF_B2);
    float* invs = (float*)(smem + OFF_IS);
    float* invo = (float*)(smem + OFF_IO);

    const int warp_m = (wid & 3) * 16;    // 0..48
    const int warp_n = (wid >> 2) * 32;   // 0..96
    const int lm_row = lane & 15;
    const int lm_col = (lane >> 4) * 8;

    const int TILES = (n + 63) >> 6;

    // ---- initial prefetch (tile 0 for this CTA) ----
    if (blockIdx.x < TILES)
        prefetch_tile(sb + OFF_AS, blockIdx.x << 6, n, tid);
    CP_COMMIT();

    // ---- one-time: weights + biases -> smem (fp16) ----
    if (tid < 128) { b1s[tid] = b1[tid]; b2s[tid] = b2[tid]; }
#pragma unroll
    for (int i = 0; i < 16; i++) {                 // W1: 256x128 fp32
        int idx = tid + 512 * i;
        int r = idx >> 5, c4 = idx & 31;
        float4 w = *(const float4*)(W1 + (size_t)r * 128 + c4 * 4);
        sts64(sb + OFF_W1 + (r * LDW + c4 * 4) * 2, pack_f16(w.x, w.y), pack_f16(w.z, w.w));
    }
#pragma unroll
    for (int i = 0; i < 8; i++) {                  // W2: 128x128 fp32
        int idx = tid + 512 * i;
        int r = idx >> 5, c4 = idx & 31;
        float4 w = *(const float4*)(W2 + (size_t)r * 128 + c4 * 4);
        sts64(sb + OFF_W2 + (r * LDW + c4 * 4) * 2, pack_f16(w.x, w.y), pack_f16(w.z, w.w));
    }

    int it = 0;
    for (int tile = blockIdx.x; tile < TILES; tile += gridDim.x, it++) {
        const int row0 = tile << 6;
        const uint32_t asb = sb + OFF_AS + (it & 1) * AS_BUF;

        // per-tile inverse counts
        if (tid < 64) {
            int r = row0 + tid;
            invs[tid] = (r < n) ? 1.f / fmaxf(g_cnt_src[r], 1.f) : 0.f;
            invo[tid] = (r < n) ? 1.f / fmaxf(g_cnt_dst[r], 1.f) : 0.f;
        }

        // prefetch next tile into other buffer
        int ntile = tile + gridDim.x;
        if (ntile < TILES)
            prefetch_tile(sb + OFF_AS + ((it & 1) ^ 1) * AS_BUF, ntile << 6, n, tid);
        CP_COMMIT();
        CP_WAIT1();            // group for current tile complete
        __syncthreads();       // As[buf], invs/invo, (it==0: weights) visible

        // ============ phase 1: As[64x256] @ W1 -> P1 (subj) / P2 (obj) =====
        float P1[4][4], P2[4][4];
#pragma unroll
        for (int j = 0; j < 4; j++)
#pragma unroll
            for (int k = 0; k < 4; k++) { P1[j][k] = 0.f; P2[j][k] = 0.f; }

#pragma unroll
        for (int ks = 0; ks < 16; ks++) {
            uint32_t a[4], bq[2][4];
            ldm_x4(asb + ((warp_m + lm_row) * LDA + ks * 16 + lm_col) * 2, a);
#pragma unroll
            for (int tb = 0; tb < 2; tb++)
                ldm_x4_t(sb + OFF_W1 + ((ks * 16 + lm_row) * LDW + warp_n + tb * 16 + lm_col) * 2, bq[tb]);
            float (*acc)[4] = (ks < 8) ? P1 : P2;
#pragma unroll
            for (int tn = 0; tn < 4; tn++)
                mma_f16(acc[tn], a, &bq[tn >> 1][(tn & 1) * 2]);
        }

        // ---- epilogue 1: relu(invs*P1 + invo*P2 + b1) -> Hs (fp16) ----
        {
            int r0 = warp_m + (lane >> 2), r1 = r0 + 8;
            int cb = warp_n + (lane & 3) * 2;
            float is0 = invs[r0], io0 = invo[r0];
            float is1 = invs[r1], io1 = invo[r1];
#pragma unroll
            for (int tn = 0; tn < 4; tn++) {
                int col = cb + tn * 8;
                float x0 = fmaxf(is0 * P1[tn][0] + io0 * P2[tn][0] + b1s[col],     0.f);
                float x1 = fmaxf(is0 * P1[tn][1] + io0 * P2[tn][1] + b1s[col + 1], 0.f);
                float x2 = fmaxf(is1 * P1[tn][2] + io1 * P2[tn][2] + b1s[col],     0.f);
                float x3 = fmaxf(is1 * P1[tn][3] + io1 * P2[tn][3] + b1s[col + 1], 0.f);
                *(uint32_t*)(smem + OFF_HS + (r0 * LDH + col) * 2) = pack_f16(x0, x1);
                *(uint32_t*)(smem + OFF_HS + (r1 * LDH + col) * 2) = pack_f16(x2, x3);
            }
        }
        __syncthreads();

        // ============ phase 2: Hs[64x128] @ W2 -> P1 =======================
#pragma unroll
        for (int j = 0; j < 4; j++)
#pragma unroll
            for (int k = 0; k < 4; k++) P1[j][k] = 0.f;

#pragma unroll
        for (int ks = 0; ks < 8; ks++) {
            uint32_t a[4], bq[2][4];
            ldm_x4(sb + OFF_HS + ((warp_m + lm_row) * LDH + ks * 16 + lm_col) * 2, a);
#pragma unroll
            for (int tb = 0; tb < 2; tb++)
                ldm_x4_t(sb + OFF_W2 + ((ks * 16 + lm_row) * LDW + warp_n + tb * 16 + lm_col) * 2, bq[tb]);
#pragma unroll
            for (int tn = 0; tn < 4; tn++)
                mma_f16(P1[tn], a, &bq[tn >> 1][(tn & 1) * 2]);
        }

        // ---- epilogue 2: sigmoid(P1 + b2) -> gmem ----
        {
            int r0 = warp_m + (lane >> 2), r1 = r0 + 8;
            int cb = warp_n + (lane & 3) * 2;
            int gr0 = row0 + r0, gr1 = row0 + r1;
#pragma unroll
            for (int tn = 0; tn < 4; tn++) {
                int col = cb + tn * 8;
                if (gr0 < n) {
                    float2 o;
                    o.x = 1.f / (1.f + __expf(-(P1[tn][0] + b2s[col])));
                    o.y = 1.f / (1.f + __expf(-(P1[tn][1] + b2s[col + 1])));
                    *(float2*)(out + (size_t)gr0 * 128 + col) = o;
                }
                if (gr1 < n) {
                    float2 o;
                    o.x = 1.f / (1.f + __expf(-(P1[tn][2] + b2s[col])));
                    o.y = 1.f / (1.f + __expf(-(P1[tn][3] + b2s[col + 1])));
                    *(float2*)(out + (size_t)gr1 * 128 + col) = o;
                }
            }
        }
        __syncthreads();   // Hs + As[buf] free for reuse / invs rewrite
    }
}

// ========================= launch ==========================================

extern "C" void kernel_launch(void* const* d_in, const int* in_sizes, int n_in,
                              void* d_out, int out_size) {
    const float* ef = (const float*)d_in[0];
    const float* W1 = (const float*)d_in[1];
    const float* b1 = (const float*)d_in[2];
    const float* W2 = (const float*)d_in[3];
    const float* b2 = (const float*)d_in[4];
    const void*  ei = d_in[5];

    long long E = in_sizes[5] / 2;
    int n = out_size / 128;

    detect_kernel<<<1, 32>>>((const int*)ei);
    zero_kernel<<<1024, 256>>>(n);

    long long warps = (E + 1) / 2;
    int sblocks = (int)((warps * 32 + 255) / 256);
    scatter_kernel<<<sblocks, 256>>>(ef, ei, E);

    cudaFuncSetAttribute(fused_mlp, cudaFuncAttributeMaxDynamicSharedMemorySize, SMEM_BYTES);
    int TILES = (n + 63) / 64;
    int grid = TILES < 148 ? TILES : 148;
    fused_mlp<<<grid, 512, SMEM_BYTES>>>(W1, b1, W2, b2, (float*)d_out, n);
}

// round 7
// speedup vs baseline: 3.0057x; 1.0038x over previous
#include <cuda_runtime.h>
#include <cuda_fp16.h>
#include <cstdint>

// ---------------------------------------------------------------------------
// TwinningEdgeAttention on GB300:
//   scatter-mean: fp16 tables via red.global.add.noftz.v4.f16x2
//   MLP: fp16 HMMA, 1024 thr/CTA (32 warps), 128-row tiles, weights resident,
//        mean-scaling at As-fill (single accumulator set, low reg pressure)
// ---------------------------------------------------------------------------

#define MAXN 65536
#define DE   128

__device__ __align__(256) __half g_subj16[MAXN * DE];
__device__ __align__(256) __half g_obj16 [MAXN * DE];
__device__ float g_cnt_src[MAXN];
__device__ float g_cnt_dst[MAXN];
__device__ int   g_idx_is64;

// ========================= helpers =========================================

__device__ __forceinline__ uint32_t smem_u32(const void* p) {
    uint32_t a;
    asm("{ .reg .u64 t; cvta.to.shared.u64 t, %1; cvt.u32.u64 %0, t; }"
        : "=r"(a) : "l"(p));
    return a;
}

__device__ __forceinline__ uint32_t pack_f16(float lo, float hi) {
    uint32_t r;
    asm("cvt.rn.f16x2.f32 %0, %1, %2;" : "=r"(r) : "f"(hi), "f"(lo));
    return r;
}

__device__ __forceinline__ void sts64(uint32_t addr, uint32_t a, uint32_t b) {
    asm volatile("st.shared.v2.b32 [%0], {%1,%2};" :: "r"(addr), "r"(a), "r"(b) : "memory");
}

__device__ __forceinline__ void sts128(uint32_t addr, uint32_t a, uint32_t b,
                                       uint32_t c, uint32_t d) {
    asm volatile("st.shared.v4.b32 [%0], {%1,%2,%3,%4};"
                 :: "r"(addr), "r"(a), "r"(b), "r"(c), "r"(d) : "memory");
}

__device__ __forceinline__ void ldm_x4(uint32_t addr, uint32_t* r) {
    asm volatile("ldmatrix.sync.aligned.m8n8.x4.shared.b16 {%0,%1,%2,%3}, [%4];"
                 : "=r"(r[0]), "=r"(r[1]), "=r"(r[2]), "=r"(r[3]) : "r"(addr));
}

__device__ __forceinline__ void ldm_x4_t(uint32_t addr, uint32_t* r) {
    asm volatile("ldmatrix.sync.aligned.m8n8.x4.trans.shared.b16 {%0,%1,%2,%3}, [%4];"
                 : "=r"(r[0]), "=r"(r[1]), "=r"(r[2]), "=r"(r[3]) : "r"(addr));
}

__device__ __forceinline__ void mma_f16(float* d, const uint32_t* a, const uint32_t* b) {
    asm volatile("mma.sync.aligned.m16n8k16.row.col.f32.f16.f16.f32 "
                 "{%0,%1,%2,%3}, {%4,%5,%6,%7}, {%8,%9}, {%0,%1,%2,%3};"
                 : "+f"(d[0]), "+f"(d[1]), "+f"(d[2]), "+f"(d[3])
                 : "r"(a[0]), "r"(a[1]), "r"(a[2]), "r"(a[3]), "r"(b[0]), "r"(b[1]));
}

__device__ __forceinline__ void red_v4h2(__half* p, uint32_t a, uint32_t b,
                                         uint32_t c, uint32_t d) {
    asm volatile("red.global.add.noftz.v4.f16x2 [%0], {%1,%2,%3,%4};"
                 :: "l"(p), "r"(a), "r"(b), "r"(c), "r"(d) : "memory");
}

// ========================= pre-GEMM kernels ================================

// zero tables + counts; block 0 thread 0 also sniffs the index dtype
__global__ void zero_kernel(int n, const int* __restrict__ ei_words) {
    if (blockIdx.x == 0 && threadIdx.x == 0) {
        int is64 = 1;
        for (int i = 0; i < 256; i++) {
            if (ei_words[2 * i + 1] != 0) { is64 = 0; break; }
        }
        g_idx_is64 = is64;
    }
    const uint4 z = make_uint4(0, 0, 0, 0);
    int total16 = n * (DE / 8);
    int stride = gridDim.x * blockDim.x;
    for (int i = blockIdx.x * blockDim.x + threadIdx.x; i < total16; i += stride) {
        reinterpret_cast<uint4*>(g_subj16)[i] = z;
        reinterpret_cast<uint4*>(g_obj16)[i]  = z;
    }
    for (int i = blockIdx.x * blockDim.x + threadIdx.x; i < n; i += stride) {
        g_cnt_src[i] = 0.f;
        g_cnt_dst[i] = 0.f;
    }
}

// One warp per TWO edges: lanes 0-15 own edge0, lanes 16-31 own edge1.
__global__ void scatter_kernel(const float* __restrict__ ef,
                               const void* __restrict__ ei_raw, long long E) {
    long long gw = (long long)(blockIdx.x * blockDim.x + threadIdx.x) >> 5;
    int lane = threadIdx.x & 31;
    int half = lane >> 4;
    int grp  = lane & 15;
    long long edge = 2 * gw + half;
    if (edge >= E) return;

    long long s, d;
    if (g_idx_is64) {
        const long long* ei = (const long long*)ei_raw;
        s = ei[edge];
        d = ei[E + edge];
    } else {
        const int* ei = (const int*)ei_raw;
        s = ei[edge];
        d = ei[E + edge];
    }

    const float4* row = (const float4*)(ef + (size_t)edge * DE + grp * 8);
    float4 v0 = row[0];
    float4 v1 = row[1];
    uint32_t h0 = pack_f16(v0.x, v0.y);
    uint32_t h1 = pack_f16(v0.z, v0.w);
    uint32_t h2 = pack_f16(v1.x, v1.y);
    uint32_t h3 = pack_f16(v1.z, v1.w);

    red_v4h2(g_subj16 + (size_t)s * DE + grp * 8, h0, h1, h2, h3);
    red_v4h2(g_obj16  + (size_t)d * DE + grp * 8, h0, h1, h2, h3);

    if (grp == 0) {
        atomicAdd(&g_cnt_src[s], 1.0f);
        atomicAdd(&g_cnt_dst[d], 1.0f);
    }
}

// ========================= fp16 HMMA MLP (32 warps) ========================
// 1024 threads = 32 warps (8 m x 4 n), warp tile 16x32, CTA tile 128x128.
// Scaling applied during As fill (raw fp16 sums * 1/cnt -> fp16 As).
// smem layout (bytes):
//   b1s[128]f32 @0, b2s[128]f32 @512
//   W1h fp16 [256][136] @2048    (69632)
//   W2h fp16 [128][136] @71680   (34816)
//   Hs  fp16 [128][136] @106496  (34816)
//   As  fp16 [128][264] @141312  (67584)  -> total 208896
static constexpr int OFF_B1 = 0, OFF_B2 = 512;
static constexpr int OFF_W1 = 2048, OFF_W2 = 71680, OFF_HS = 106496, OFF_AS = 141312;
static constexpr int LDW = 136, LDH = 136, LDA = 264;
static constexpr int SMEM_BYTES = 208896;

__global__ void __launch_bounds__(1024, 1)
fused_mlp(const float* __restrict__ W1, const float* __restrict__ b1,
          const float* __restrict__ W2, const float* __restrict__ b2,
          float* __restrict__ out, int n)
{
    extern __shared__ char smem[];
    const uint32_t sb = smem_u32(smem);
    const int tid = threadIdx.x, wid = tid >> 5, lane = tid & 31;

    float* b1s = (float*)(smem + OFF_B1);
    float* b2s = (float*)(smem + OFF_B2);

    const int warp_m = (wid & 7) * 16;    // 0..112
    const int warp_n = (wid >> 3) * 32;   // 0..96
    const int lm_row = lane & 15;
    const int lm_col = (lane >> 4) * 8;

    // ---- one-time: weights + biases -> smem (fp16) ----
    if (tid < 128) { b1s[tid] = b1[tid]; b2s[tid] = b2[tid]; }
#pragma unroll
    for (int i = 0; i < 8; i++) {                  // W1: 256x128 fp32
        int idx = tid + 1024 * i;
        int r = idx >> 5, c4 = idx & 31;
        float4 w = *(const float4*)(W1 + (size_t)r * 128 + c4 * 4);
        sts64(sb + OFF_W1 + (r * LDW + c4 * 4) * 2, pack_f16(w.x, w.y), pack_f16(w.z, w.w));
    }
#pragma unroll
    for (int i = 0; i < 4; i++) {                  // W2: 128x128 fp32
        int idx = tid + 1024 * i;
        int r = idx >> 5, c4 = idx & 31;
        float4 w = *(const float4*)(W2 + (size_t)r * 128 + c4 * 4);
        sts64(sb + OFF_W2 + (r * LDW + c4 * 4) * 2, pack_f16(w.x, w.y), pack_f16(w.z, w.w));
    }

    const int TILES = (n + 127) >> 7;
    for (int tile = blockIdx.x; tile < TILES; tile += gridDim.x) {
        const int row0 = tile << 7;

        // ---- As fill: scaled means, fp16, [128][256] (LDA padded 264) ----
        // 4096 16B chunks, 4 per thread. inv-count fetched per chunk (L2 hit).
#pragma unroll
        for (int i = 0; i < 4; i++) {
            int idx = tid + 1024 * i;             // 0..4095
            int r = idx >> 5, c8 = idx & 31;      // r:0..127, c8:0..31
            int gr = row0 + r;
            uint32_t o0 = 0, o1 = 0, o2 = 0, o3 = 0;
            if (gr < n) {
                const __half* src;
                float cnt;
                if (c8 < 16) {
                    src = g_subj16 + (size_t)gr * DE + c8 * 8;
                    cnt = g_cnt_src[gr];
                } else {
                    src = g_obj16 + (size_t)gr * DE + (c8 - 16) * 8;
                    cnt = g_cnt_dst[gr];
                }
                float s = 1.f / fmaxf(cnt, 1.f);
                uint4 raw = *(const uint4*)src;
                const __half2* h2 = (const __half2*)&raw;
                float2 f0 = __half22float2(h2[0]);
                float2 f1 = __half22float2(h2[1]);
                float2 f2 = __half22float2(h2[2]);
                float2 f3 = __half22float2(h2[3]);
                o0 = pack_f16(f0.x * s, f0.y * s);
                o1 = pack_f16(f1.x * s, f1.y * s);
                o2 = pack_f16(f2.x * s, f2.y * s);
                o3 = pack_f16(f3.x * s, f3.y * s);
            }
            sts128(sb + OFF_AS + (r * LDA + c8 * 8) * 2, o0, o1, o2, o3);
        }
        __syncthreads();

        // ============ phase 1: As[128x256] @ W1 -> P ======================
        float P[4][4];
#pragma unroll
        for (int j = 0; j < 4; j++)
#pragma unroll
            for (int k = 0; k < 4; k++) P[j][k] = 0.f;

#pragma unroll
        for (int ks = 0; ks < 16; ks++) {
            uint32_t a[4], bq[2][4];
            ldm_x4(sb + OFF_AS + ((warp_m + lm_row) * LDA + ks * 16 + lm_col) * 2, a);
#pragma unroll
            for (int tb = 0; tb < 2; tb++)
                ldm_x4_t(sb + OFF_W1 + ((ks * 16 + lm_row) * LDW + warp_n + tb * 16 + lm_col) * 2, bq[tb]);
#pragma unroll
            for (int tn = 0; tn < 4; tn++)
                mma_f16(P[tn], a, &bq[tn >> 1][(tn & 1) * 2]);
        }

        // ---- epilogue 1: relu(P + b1) -> Hs (fp16) ----
        {
            int r0 = warp_m + (lane >> 2), r1 = r0 + 8;
            int cb = warp_n + (lane & 3) * 2;
#pragma unroll
            for (int tn = 0; tn < 4; tn++) {
                int col = cb + tn * 8;
                float x0 = fmaxf(P[tn][0] + b1s[col],     0.f);
                float x1 = fmaxf(P[tn][1] + b1s[col + 1], 0.f);
                float x2 = fmaxf(P[tn][2] + b1s[col],     0.f);
                float x3 = fmaxf(P[tn][3] + b1s[col + 1], 0.f);
                *(uint32_t*)(smem + OFF_HS + (r0 * LDH + col) * 2) = pack_f16(x0, x1);
                *(uint32_t*)(smem + OFF_HS + (r1 * LDH + col) * 2) = pack_f16(x2, x3);
            }
        }
        __syncthreads();

        // ============ phase 2: Hs[128x128] @ W2 -> P ======================
#pragma unroll
        for (int j = 0; j < 4; j++)
#pragma unroll
            for (int k = 0; k < 4; k++) P[j][k] = 0.f;

#pragma unroll
        for (int ks = 0; ks < 8; ks++) {
            uint32_t a[4], bq[2][4];
            ldm_x4(sb + OFF_HS + ((warp_m + lm_row) * LDH + ks * 16 + lm_col) * 2, a);
#pragma unroll
            for (int tb = 0; tb < 2; tb++)
                ldm_x4_t(sb + OFF_W2 + ((ks * 16 + lm_row) * LDW + warp_n + tb * 16 + lm_col) * 2, bq[tb]);
#pragma unroll
            for (int tn = 0; tn < 4; tn++)
                mma_f16(P[tn], a, &bq[tn >> 1][(tn & 1) * 2]);
        }

        // ---- epilogue 2: sigmoid(P + b2) -> gmem ----
        {
            int r0 = warp_m + (lane >> 2), r1 = r0 + 8;
            int cb = warp_n + (lane & 3) * 2;
            int gr0 = row0 + r0, gr1 = row0 + r1;
#pragma unroll
            for (int tn = 0; tn < 4; tn++) {
                int col = cb + tn * 8;
                if (gr0 < n) {
                    float2 o;
                    o.x = 1.f / (1.f + __expf(-(P[tn][0] + b2s[col])));
                    o.y = 1.f / (1.f + __expf(-(P[tn][1] + b2s[col + 1])));
                    *(float2*)(out + (size_t)gr0 * 128 + col) = o;
                }
                if (gr1 < n) {
                    float2 o;
                    o.x = 1.f / (1.f + __expf(-(P[tn][2] + b2s[col])));
                    o.y = 1.f / (1.f + __expf(-(P[tn][3] + b2s[col + 1])));
                    *(float2*)(out + (size_t)gr1 * 128 + col) = o;
                }
            }
        }
        __syncthreads();   // As/Hs free for next tile
    }
}

// ========================= launch ==========================================

extern "C" void kernel_launch(void* const* d_in, const int* in_sizes, int n_in,
                              void* d_out, int out_size) {
    const float* ef = (const float*)d_in[0];
    const float* W1 = (const float*)d_in[1];
    const float* b1 = (const float*)d_in[2];
    const float* W2 = (const float*)d_in[3];
    const float* b2 = (const float*)d_in[4];
    const void*  ei = d_in[5];

    long long E = in_sizes[5] / 2;
    int n = out_size / 128;

    zero_kernel<<<1024, 256>>>(n, (const int*)ei);

    long long warps = (E + 1) / 2;
    int sblocks = (int)((warps * 32 + 255) / 256);
    scatter_kernel<<<sblocks, 256>>>(ef, ei, E);

    cudaFuncSetAttribute(fused_mlp, cudaFuncAttributeMaxDynamicSharedMemorySize, SMEM_BYTES);
    int TILES = (n + 127) / 128;
    int grid = TILES < 148 ? TILES : 148;
    fused_mlp<<<grid, 1024, SMEM_BYTES>>>(W1, b1, W2, b2, (float*)d_out, n);
}